// round 1
// baseline (speedup 1.0000x reference)
#include <cuda_runtime.h>
#include <cstdint>

#define SQ 2048
#define DD 1024
#define HH 8

// Scratch (static device globals: allocation-free)
__device__ float g_tmp[SQ * DD];            // relu(relations@w1+b1)
__device__ float g_rel[SQ * DD];            // rel encoder output
__device__ float g_scoresP[HH * SQ * DD];   // permuted scores: [h][t][d] = scores[t>>8][(t&255)*8+h][d]
__device__ float g_attn[(size_t)HH * SQ * SQ]; // rel_scores -> softmax in place
__device__ float g_ctx[SQ * (HH * DD)];     // [s][h*D+d]

// ---------------- K1: tmp = relu(relations @ re_w1 + re_b1) ----------------
__global__ void relenc1_kernel(const float* __restrict__ relations,
                               const float* __restrict__ w1,
                               const float* __restrict__ b1,
                               float* __restrict__ out) {
    int idx = blockIdx.x * blockDim.x + threadIdx.x;   // over SQ*DD
    int s = idx >> 10, j = idx & 1023;
    const float* r = relations + s * 4;
    float acc = b1[j];
    acc = fmaf(r[0], w1[j],        acc);
    acc = fmaf(r[1], w1[1024 + j], acc);
    acc = fmaf(r[2], w1[2048 + j], acc);
    acc = fmaf(r[3], w1[3072 + j], acc);
    out[idx] = fmaxf(acc, 0.0f);
}

// ---------------- Generic SGEMM ----------------
// C[M,N] = A[M,K] * (BT ? B[N,K]^T : B[K,N])     (no bounds checks: M,N % 128 == 0, K % 16 == 0)
// EPI: 0 = plain, 1 = +bias[col], 2 = scatter rows for scoresP permutation (uses z = blockIdx.z)
#define BM 128
#define BN 128
#define BK 16
#define PAD 4

#define LOAD_TILE(kt, bf) do {                                                          \
    int k0 = (kt) * BK;                                                                 \
    _Pragma("unroll")                                                                   \
    for (int p = 0; p < 2; p++) {                                                       \
        int r = arow + p * 64;                                                          \
        const float4 va = *(const float4*)(A + (size_t)(bm0 + r) * lda + k0 + acol);    \
        As[bf][acol + 0][r] = va.x; As[bf][acol + 1][r] = va.y;                         \
        As[bf][acol + 2][r] = va.z; As[bf][acol + 3][r] = va.w;                         \
    }                                                                                   \
    if (BT) {                                                                           \
        _Pragma("unroll")                                                               \
        for (int p = 0; p < 2; p++) {                                                   \
            int r = arow + p * 64;                                                      \
            const float4 vb = *(const float4*)(Bp + (size_t)(bn0 + r) * ldb + k0 + acol);\
            Bs[bf][acol + 0][r] = vb.x; Bs[bf][acol + 1][r] = vb.y;                     \
            Bs[bf][acol + 2][r] = vb.z; Bs[bf][acol + 3][r] = vb.w;                     \
        }                                                                               \
    } else {                                                                            \
        _Pragma("unroll")                                                               \
        for (int p = 0; p < 2; p++) {                                                   \
            int r = brow + p * 8;                                                       \
            *(float4*)&Bs[bf][r][bcol] =                                                \
                *(const float4*)(Bp + (size_t)(k0 + r) * ldb + bn0 + bcol);             \
        }                                                                               \
    }                                                                                   \
} while (0)

template<bool BT, int EPI>
__global__ __launch_bounds__(256, 2)
void sgemm_kernel(const float* __restrict__ Ab, const float* __restrict__ Bb,
                  float* __restrict__ Cb, const float* __restrict__ bias,
                  int K, int ldb, int ldc,
                  long long sA, long long sB, long long sC)
{
    __shared__ float As[2][BK][BM + PAD];
    __shared__ float Bs[2][BK][BN + PAD];

    const int z = blockIdx.z;
    const float* A  = Ab + (size_t)z * sA;
    const float* Bp = Bb + (size_t)z * sB;
    float*       C  = Cb + (size_t)z * sC;

    const int bm0 = blockIdx.y * BM;
    const int bn0 = blockIdx.x * BN;
    const int tid = threadIdx.x;
    const int lda = K;

    const int arow = tid >> 2;          // 0..63
    const int acol = (tid & 3) << 2;    // 0,4,8,12
    const int brow = tid >> 5;          // 0..7  (NN B loader)
    const int bcol = (tid & 31) << 2;   // 0..124

    const int tm0 = (tid >> 4) << 3;
    const int tn0 = (tid & 15) << 3;

    float acc[8][8];
#pragma unroll
    for (int i = 0; i < 8; i++)
#pragma unroll
        for (int j = 0; j < 8; j++) acc[i][j] = 0.0f;

    const int nk = K / BK;
    LOAD_TILE(0, 0);
    __syncthreads();

    int buf = 0;
    for (int kt = 0; kt < nk; kt++) {
        if (kt + 1 < nk) { LOAD_TILE(kt + 1, buf ^ 1); }
#pragma unroll
        for (int k = 0; k < BK; k++) {
            float4 a0 = *(const float4*)&As[buf][k][tm0];
            float4 a1 = *(const float4*)&As[buf][k][tm0 + 4];
            float4 b0 = *(const float4*)&Bs[buf][k][tn0];
            float4 b1 = *(const float4*)&Bs[buf][k][tn0 + 4];
            float av[8] = {a0.x, a0.y, a0.z, a0.w, a1.x, a1.y, a1.z, a1.w};
            float bv[8] = {b0.x, b0.y, b0.z, b0.w, b1.x, b1.y, b1.z, b1.w};
#pragma unroll
            for (int i = 0; i < 8; i++)
#pragma unroll
                for (int j = 0; j < 8; j++)
                    acc[i][j] = fmaf(av[i], bv[j], acc[i][j]);
        }
        __syncthreads();
        buf ^= 1;
    }

    // Epilogue
    float bvals[8];
    if (EPI == 1) {
#pragma unroll
        for (int j = 0; j < 8; j++) bvals[j] = __ldg(&bias[bn0 + tn0 + j]);
    }
#pragma unroll
    for (int i = 0; i < 8; i++) {
        int m = bm0 + tm0 + i;
        size_t rowoff;
        if (EPI == 2) {
            // dst row in scoresP: (m&7)*2048 + z*256 + (m>>3), ldc = 1024
            int dst = ((m & 7) << 11) + (z << 8) + (m >> 3);
            rowoff = (size_t)dst * ldc;
        } else {
            rowoff = (size_t)m * ldc;
        }
        float* cp = C + rowoff + bn0 + tn0;
        float4 o0, o1;
        if (EPI == 1) {
            o0 = make_float4(acc[i][0] + bvals[0], acc[i][1] + bvals[1],
                             acc[i][2] + bvals[2], acc[i][3] + bvals[3]);
            o1 = make_float4(acc[i][4] + bvals[4], acc[i][5] + bvals[5],
                             acc[i][6] + bvals[6], acc[i][7] + bvals[7]);
        } else {
            o0 = make_float4(acc[i][0], acc[i][1], acc[i][2], acc[i][3]);
            o1 = make_float4(acc[i][4], acc[i][5], acc[i][6], acc[i][7]);
        }
        *(float4*)(cp)     = o0;
        *(float4*)(cp + 4) = o1;
    }
}

// ---------------- Softmax over rows of length 2048 ----------------
__global__ void softmax_kernel(float* __restrict__ data) {
    __shared__ float red[8];
    size_t row = blockIdx.x;
    float* p = data + row * (size_t)SQ;
    int tid = threadIdx.x;

    float v[8];
    float mx = -3.4e38f;
#pragma unroll
    for (int i = 0; i < 8; i++) { v[i] = p[tid + i * 256]; mx = fmaxf(mx, v[i]); }
#pragma unroll
    for (int o = 16; o; o >>= 1) mx = fmaxf(mx, __shfl_xor_sync(0xffffffffu, mx, o));
    if ((tid & 31) == 0) red[tid >> 5] = mx;
    __syncthreads();
    mx = red[0];
#pragma unroll
    for (int i = 1; i < 8; i++) mx = fmaxf(mx, red[i]);

    float sum = 0.0f;
#pragma unroll
    for (int i = 0; i < 8; i++) { v[i] = expf(v[i] - mx); sum += v[i]; }
#pragma unroll
    for (int o = 16; o; o >>= 1) sum += __shfl_xor_sync(0xffffffffu, sum, o);
    __syncthreads();            // red reuse
    if ((tid & 31) == 0) red[tid >> 5] = sum;
    __syncthreads();
    sum = red[0];
#pragma unroll
    for (int i = 1; i < 8; i++) sum += red[i];
    float inv = 1.0f / sum;
#pragma unroll
    for (int i = 0; i < 8; i++) p[tid + i * 256] = v[i] * inv;
}

// ---------------- Launch ----------------
extern "C" void kernel_launch(void* const* d_in, const int* in_sizes, int n_in,
                              void* d_out, int out_size) {
    const float* x      = (const float*)d_in[0];
    const float* rels   = (const float*)d_in[1];
    const float* re_w1  = (const float*)d_in[2];
    const float* re_b1  = (const float*)d_in[3];
    const float* re_w2  = (const float*)d_in[4];
    const float* re_b2  = (const float*)d_in[5];
    const float* attn_w = (const float*)d_in[6];
    const float* out_w  = (const float*)d_in[7];
    const float* out_b  = (const float*)d_in[8];
    float* out = (float*)d_out;

    float *tmp, *rel, *scoresP, *attn, *ctx;
    cudaGetSymbolAddress((void**)&tmp,     g_tmp);
    cudaGetSymbolAddress((void**)&rel,     g_rel);
    cudaGetSymbolAddress((void**)&scoresP, g_scoresP);
    cudaGetSymbolAddress((void**)&attn,    g_attn);
    cudaGetSymbolAddress((void**)&ctx,     g_ctx);

    // K1: tmp = relu(relations @ re_w1 + re_b1)
    relenc1_kernel<<<(SQ * DD) / 256, 256>>>(rels, re_w1, re_b1, tmp);

    // K2: rel = tmp @ re_w2 + re_b2            [2048,1024,1024]
    sgemm_kernel<false, 1><<<dim3(DD / BN, SQ / BM, 1), 256>>>(
        tmp, re_w2, rel, re_b2, 1024, 1024, 1024, 0, 0, 0);

    // K3: scoresP (permuted) = x @ attn_w[h]   [2048,1024,1024] x8, scatter epilogue
    sgemm_kernel<false, 2><<<dim3(DD / BN, SQ / BM, HH), 256>>>(
        x, attn_w, scoresP, nullptr, 1024, 1024, 1024,
        0, (long long)DD * DD, 0);

    // K4: rel_scores[h] = rel @ scoresP[h]^T   [2048,2048,1024] x8
    sgemm_kernel<true, 0><<<dim3(SQ / BN, SQ / BM, HH), 256>>>(
        rel, scoresP, attn, nullptr, 1024, 1024, 2048,
        0, (long long)SQ * DD, (long long)SQ * SQ);

    // K5: softmax rows
    softmax_kernel<<<HH * SQ, 256>>>(attn);

    // K6: ctx[s][h*D+d] = attn[h] @ x          [2048,1024,2048] x8
    sgemm_kernel<false, 0><<<dim3(DD / BN, SQ / BM, HH), 256>>>(
        attn, x, ctx, nullptr, 2048, 1024, 8192,
        (long long)SQ * SQ, 0, (long long)DD);

    // K7: out = ctx @ out_w + out_b            [2048,1024,8192]
    sgemm_kernel<false, 1><<<dim3(DD / BN, SQ / BM, 1), 256>>>(
        ctx, out_w, out, out_b, 8192, 1024, 1024, 0, 0, 0);
}

// round 2
// speedup vs baseline: 1.0034x; 1.0034x over previous
#include <cuda_runtime.h>
#include <cstdint>

#define SQ 2048
#define DD 1024
#define HH 8

// Scratch (static device globals: allocation-free)
__device__ float g_tmp[SQ * DD];            // relu(relations@w1+b1)
__device__ float g_rel[SQ * DD];            // rel encoder output
__device__ float g_scoresP[HH * SQ * DD];   // permuted scores: [h][t][d] = scores[t>>8][(t&255)*8+h][d]
__device__ float g_attn[(size_t)HH * SQ * SQ]; // rel_scores -> softmax in place
__device__ float g_ctx[SQ * (HH * DD)];     // [s][h*D+d]

// ---------------- K1: tmp = relu(relations @ re_w1 + re_b1) ----------------
__global__ void relenc1_kernel(const float* __restrict__ relations,
                               const float* __restrict__ w1,
                               const float* __restrict__ b1,
                               float* __restrict__ out) {
    int idx = blockIdx.x * blockDim.x + threadIdx.x;   // over SQ*DD
    int s = idx >> 10, j = idx & 1023;
    const float* r = relations + s * 4;
    float acc = b1[j];
    acc = fmaf(r[0], w1[j],        acc);
    acc = fmaf(r[1], w1[1024 + j], acc);
    acc = fmaf(r[2], w1[2048 + j], acc);
    acc = fmaf(r[3], w1[3072 + j], acc);
    out[idx] = fmaxf(acc, 0.0f);
}

// ---------------- Generic SGEMM ----------------
// C[M,N] = A[M,K] * (BT ? B[N,K]^T : B[K,N])     (no bounds checks: M,N % 128 == 0, K % 16 == 0)
// EPI: 0 = plain, 1 = +bias[col], 2 = scatter rows for scoresP permutation (uses z = blockIdx.z)
#define BM 128
#define BN 128
#define BK 16
#define PAD 4

#define LOAD_TILE(kt, bf) do {                                                          \
    int k0 = (kt) * BK;                                                                 \
    _Pragma("unroll")                                                                   \
    for (int p = 0; p < 2; p++) {                                                       \
        int r = arow + p * 64;                                                          \
        const float4 va = *(const float4*)(A + (size_t)(bm0 + r) * lda + k0 + acol);    \
        As[bf][acol + 0][r] = va.x; As[bf][acol + 1][r] = va.y;                         \
        As[bf][acol + 2][r] = va.z; As[bf][acol + 3][r] = va.w;                         \
    }                                                                                   \
    if (BT) {                                                                           \
        _Pragma("unroll")                                                               \
        for (int p = 0; p < 2; p++) {                                                   \
            int r = arow + p * 64;                                                      \
            const float4 vb = *(const float4*)(Bp + (size_t)(bn0 + r) * ldb + k0 + acol);\
            Bs[bf][acol + 0][r] = vb.x; Bs[bf][acol + 1][r] = vb.y;                     \
            Bs[bf][acol + 2][r] = vb.z; Bs[bf][acol + 3][r] = vb.w;                     \
        }                                                                               \
    } else {                                                                            \
        _Pragma("unroll")                                                               \
        for (int p = 0; p < 2; p++) {                                                   \
            int r = brow + p * 8;                                                       \
            *(float4*)&Bs[bf][r][bcol] =                                                \
                *(const float4*)(Bp + (size_t)(k0 + r) * ldb + bn0 + bcol);             \
        }                                                                               \
    }                                                                                   \
} while (0)

template<bool BT, int EPI>
__global__ __launch_bounds__(256, 2)
void sgemm_kernel(const float* __restrict__ Ab, const float* __restrict__ Bb,
                  float* __restrict__ Cb, const float* __restrict__ bias,
                  int K, int ldb, int ldc,
                  long long sA, long long sB, long long sC)
{
    __shared__ float As[2][BK][BM + PAD];
    __shared__ float Bs[2][BK][BN + PAD];

    const int z = blockIdx.z;
    const float* A  = Ab + (size_t)z * sA;
    const float* Bp = Bb + (size_t)z * sB;
    float*       C  = Cb + (size_t)z * sC;

    const int bm0 = blockIdx.y * BM;
    const int bn0 = blockIdx.x * BN;
    const int tid = threadIdx.x;
    const int lda = K;

    const int arow = tid >> 2;          // 0..63
    const int acol = (tid & 3) << 2;    // 0,4,8,12
    const int brow = tid >> 5;          // 0..7  (NN B loader)
    const int bcol = (tid & 31) << 2;   // 0..124

    const int tm0 = (tid >> 4) << 3;
    const int tn0 = (tid & 15) << 3;

    float acc[8][8];
#pragma unroll
    for (int i = 0; i < 8; i++)
#pragma unroll
        for (int j = 0; j < 8; j++) acc[i][j] = 0.0f;

    const int nk = K / BK;
    LOAD_TILE(0, 0);
    __syncthreads();

    int buf = 0;
    for (int kt = 0; kt < nk; kt++) {
        if (kt + 1 < nk) { LOAD_TILE(kt + 1, buf ^ 1); }
#pragma unroll
        for (int k = 0; k < BK; k++) {
            float4 a0 = *(const float4*)&As[buf][k][tm0];
            float4 a1 = *(const float4*)&As[buf][k][tm0 + 4];
            float4 b0 = *(const float4*)&Bs[buf][k][tn0];
            float4 b1 = *(const float4*)&Bs[buf][k][tn0 + 4];
            float av[8] = {a0.x, a0.y, a0.z, a0.w, a1.x, a1.y, a1.z, a1.w};
            float bv[8] = {b0.x, b0.y, b0.z, b0.w, b1.x, b1.y, b1.z, b1.w};
#pragma unroll
            for (int i = 0; i < 8; i++)
#pragma unroll
                for (int j = 0; j < 8; j++)
                    acc[i][j] = fmaf(av[i], bv[j], acc[i][j]);
        }
        __syncthreads();
        buf ^= 1;
    }

    // Epilogue
    float bvals[8];
    if (EPI == 1) {
#pragma unroll
        for (int j = 0; j < 8; j++) bvals[j] = __ldg(&bias[bn0 + tn0 + j]);
    }
#pragma unroll
    for (int i = 0; i < 8; i++) {
        int m = bm0 + tm0 + i;
        size_t rowoff;
        if (EPI == 2) {
            // dst row in scoresP: (m&7)*2048 + z*256 + (m>>3), ldc = 1024
            int dst = ((m & 7) << 11) + (z << 8) + (m >> 3);
            rowoff = (size_t)dst * ldc;
        } else {
            rowoff = (size_t)m * ldc;
        }
        float* cp = C + rowoff + bn0 + tn0;
        float4 o0, o1;
        if (EPI == 1) {
            o0 = make_float4(acc[i][0] + bvals[0], acc[i][1] + bvals[1],
                             acc[i][2] + bvals[2], acc[i][3] + bvals[3]);
            o1 = make_float4(acc[i][4] + bvals[4], acc[i][5] + bvals[5],
                             acc[i][6] + bvals[6], acc[i][7] + bvals[7]);
        } else {
            o0 = make_float4(acc[i][0], acc[i][1], acc[i][2], acc[i][3]);
            o1 = make_float4(acc[i][4], acc[i][5], acc[i][6], acc[i][7]);
        }
        *(float4*)(cp)     = o0;
        *(float4*)(cp + 4) = o1;
    }
}

// ---------------- Softmax over rows of length 2048 ----------------
__global__ void softmax_kernel(float* __restrict__ data) {
    __shared__ float red[8];
    size_t row = blockIdx.x;
    float* p = data + row * (size_t)SQ;
    int tid = threadIdx.x;

    float v[8];
    float mx = -3.4e38f;
#pragma unroll
    for (int i = 0; i < 8; i++) { v[i] = p[tid + i * 256]; mx = fmaxf(mx, v[i]); }
#pragma unroll
    for (int o = 16; o; o >>= 1) mx = fmaxf(mx, __shfl_xor_sync(0xffffffffu, mx, o));
    if ((tid & 31) == 0) red[tid >> 5] = mx;
    __syncthreads();
    mx = red[0];
#pragma unroll
    for (int i = 1; i < 8; i++) mx = fmaxf(mx, red[i]);

    float sum = 0.0f;
#pragma unroll
    for (int i = 0; i < 8; i++) { v[i] = expf(v[i] - mx); sum += v[i]; }
#pragma unroll
    for (int o = 16; o; o >>= 1) sum += __shfl_xor_sync(0xffffffffu, sum, o);
    __syncthreads();            // red reuse
    if ((tid & 31) == 0) red[tid >> 5] = sum;
    __syncthreads();
    sum = red[0];
#pragma unroll
    for (int i = 1; i < 8; i++) sum += red[i];
    float inv = 1.0f / sum;
#pragma unroll
    for (int i = 0; i < 8; i++) p[tid + i * 256] = v[i] * inv;
}

// ---------------- Launch ----------------
extern "C" void kernel_launch(void* const* d_in, const int* in_sizes, int n_in,
                              void* d_out, int out_size) {
    const float* x      = (const float*)d_in[0];
    const float* rels   = (const float*)d_in[1];
    const float* re_w1  = (const float*)d_in[2];
    const float* re_b1  = (const float*)d_in[3];
    const float* re_w2  = (const float*)d_in[4];
    const float* re_b2  = (const float*)d_in[5];
    const float* attn_w = (const float*)d_in[6];
    const float* out_w  = (const float*)d_in[7];
    const float* out_b  = (const float*)d_in[8];
    float* out = (float*)d_out;

    float *tmp, *rel, *scoresP, *attn, *ctx;
    cudaGetSymbolAddress((void**)&tmp,     g_tmp);
    cudaGetSymbolAddress((void**)&rel,     g_rel);
    cudaGetSymbolAddress((void**)&scoresP, g_scoresP);
    cudaGetSymbolAddress((void**)&attn,    g_attn);
    cudaGetSymbolAddress((void**)&ctx,     g_ctx);

    // K1: tmp = relu(relations @ re_w1 + re_b1)
    relenc1_kernel<<<(SQ * DD) / 256, 256>>>(rels, re_w1, re_b1, tmp);

    // K2: rel = tmp @ re_w2 + re_b2            [2048,1024,1024]
    sgemm_kernel<false, 1><<<dim3(DD / BN, SQ / BM, 1), 256>>>(
        tmp, re_w2, rel, re_b2, 1024, 1024, 1024, 0, 0, 0);

    // K3: scoresP (permuted) = x @ attn_w[h]   [2048,1024,1024] x8, scatter epilogue
    sgemm_kernel<false, 2><<<dim3(DD / BN, SQ / BM, HH), 256>>>(
        x, attn_w, scoresP, nullptr, 1024, 1024, 1024,
        0, (long long)DD * DD, 0);

    // K4: rel_scores[h] = rel @ scoresP[h]^T   [2048,2048,1024] x8
    sgemm_kernel<true, 0><<<dim3(SQ / BN, SQ / BM, HH), 256>>>(
        rel, scoresP, attn, nullptr, 1024, 1024, 2048,
        0, (long long)SQ * DD, (long long)SQ * SQ);

    // K5: softmax rows
    softmax_kernel<<<HH * SQ, 256>>>(attn);

    // K6: ctx[s][h*D+d] = attn[h] @ x          [2048,1024,2048] x8
    sgemm_kernel<false, 0><<<dim3(DD / BN, SQ / BM, HH), 256>>>(
        attn, x, ctx, nullptr, 2048, 1024, 8192,
        (long long)SQ * SQ, 0, (long long)DD);

    // K7: out = ctx @ out_w + out_b            [2048,1024,8192]
    sgemm_kernel<false, 1><<<dim3(DD / BN, SQ / BM, 1), 256>>>(
        ctx, out_w, out, out_b, 8192, 1024, 1024, 0, 0, 0);
}